// round 16
// baseline (speedup 1.0000x reference)
#include <cuda_runtime.h>
#include <cuda_bf16.h>
#include <cstdint>
#include <math.h>
#include <mma.h>

using namespace nvcuda;
typedef __nv_bfloat16 bf16;

static constexpr int B_  = 4;
static constexpr int L_  = 2048;
static constexpr int HID = 256;   // hidden after input proj
static constexpr int DI  = 512;   // d_inner
static constexpr int NS  = 16;    // d_state
static constexpr int RK  = 16;    // dt_rank
static constexpr int NCH = 64;    // chunks
static constexpr int LC  = 32;    // chunk length (NCH*LC == L_)
static constexpr int BL  = B_ * L_;   // 8192

// ---------------- scratch (device globals; no allocations allowed) -------------
__device__ __align__(256) float g_xz  [2 * BL * 2 * DI];    // per-dir xz (xi | z)
__device__ __align__(256) float g_dbc [2 * 2 * BL * 48];    // x-proj out, 2 K-slabs
__device__ __align__(256) float g_S   [2 * NCH * B_ * DI * NS];
__device__ __align__(256) float g_P   [2 * NCH * B_ * DI * NS];
__device__ __align__(256) float g_Kc  [2 * NCH * B_ * DI * NS];
__device__ __align__(256) float g_al  [2 * NCH * B_ * DI];
__device__ __align__(256) float g_pool[2 * B_ * DI];
__device__ __align__(256) float g_embd[B_ * 2 * HID];
// bf16 hi/lo split operands
__device__ __align__(256) bf16 g_xh  [BL * 512],        g_xl  [BL * 512];
__device__ __align__(256) bf16 g_hh  [BL * HID],        g_hl  [BL * HID];
__device__ __align__(256) bf16 g_uh  [2 * BL * DI],     g_ul  [2 * BL * DI];
__device__ __align__(256) bf16 g_ipwh[HID * 512],       g_ipwl[HID * 512];
__device__ __align__(256) bf16 g_inwh[2 * 1024 * HID],  g_inwl[2 * 1024 * HID];
__device__ __align__(256) bf16 g_xpwh[2 * 48 * 512],    g_xpwl[2 * 48 * 512];

// ---------------- packed f32x2 + fast-transcendental helpers -------------------
__device__ __forceinline__ float2 fma2(float2 a, float2 b, float2 c) {
    float2 r;
    asm("fma.rn.f32x2 %0, %1, %2, %3;"
        : "=l"(*reinterpret_cast<unsigned long long*>(&r))
        : "l"(*reinterpret_cast<unsigned long long*>(&a)),
          "l"(*reinterpret_cast<unsigned long long*>(&b)),
          "l"(*reinterpret_cast<unsigned long long*>(&c)));
    return r;
}
__device__ __forceinline__ float2 mul2(float2 a, float2 b) {
    float2 r;
    asm("mul.rn.f32x2 %0, %1, %2;"
        : "=l"(*reinterpret_cast<unsigned long long*>(&r))
        : "l"(*reinterpret_cast<unsigned long long*>(&a)),
          "l"(*reinterpret_cast<unsigned long long*>(&b)));
    return r;
}
__device__ __forceinline__ float ex2f(float x) {
    float r; asm("ex2.approx.f32 %0, %1;" : "=f"(r) : "f"(x)); return r;
}
__device__ __forceinline__ float lg2f(float x) {
    float r; asm("lg2.approx.f32 %0, %1;" : "=f"(r) : "f"(x)); return r;
}
__device__ __forceinline__ float rcpf(float x) {
    float r; asm("rcp.approx.f32 %0, %1;" : "=f"(r) : "f"(x)); return r;
}

// ------- fp32 -> bf16 (hi, lo) splits: 8 elems/thread, packed uint4 stores -----
__global__ void split_all(const float* __restrict__ w0, bf16* __restrict__ h0, bf16* __restrict__ l0, int n0,
                          const float* __restrict__ w1, bf16* __restrict__ h1, bf16* __restrict__ l1, int n1,
                          const float* __restrict__ w2, bf16* __restrict__ h2, bf16* __restrict__ l2, int n2,
                          const float* __restrict__ w3, bf16* __restrict__ h3, bf16* __restrict__ l3, int n3)
{
    int i = (blockIdx.x * blockDim.x + threadIdx.x) * 8;
    const float* s; bf16 *ph, *pl; int off;
    if (i < n0)                     { s = w0; ph = h0; pl = l0; off = i; }
    else if (i < n0 + n1)           { s = w1; ph = h1; pl = l1; off = i - n0; }
    else if (i < n0 + n1 + n2)      { s = w2; ph = h2; pl = l2; off = i - n0 - n1; }
    else if (i < n0 + n1 + n2 + n3) { s = w3; ph = h3; pl = l3; off = i - n0 - n1 - n2; }
    else return;
    float4 va = *(const float4*)(s + off);
    float4 vb = *(const float4*)(s + off + 4);
    float vv[8] = {va.x, va.y, va.z, va.w, vb.x, vb.y, vb.z, vb.w};
    bf16 hb[8], lb[8];
#pragma unroll
    for (int j = 0; j < 8; j++) {
        bf16 h = __float2bfloat16(vv[j]);
        hb[j] = h;
        lb[j] = __float2bfloat16(vv[j] - __bfloat162float(h));
    }
    *(uint4*)(ph + off) = *(const uint4*)hb;
    *(uint4*)(pl + off) = *(const uint4*)lb;
}

// =================== bf16 tensor-core GEMM (3-term split), BK=32, 2-stage ======
// C[M,N] = A[M,K] @ W[N,K]^T (+bias), operands as bf16 (hi, lo) pairs.
// Product al*bh + ah*bl + ah*bh -> ~2^-17 relative error; fp32 accumulate.
// Block tile 128 x (64*NJ) x 32; 256 threads = 8 warps in 2(m) x 4(n).
// GUARD mode: N<=64 single N-tile; blockIdx.x selects a K-slice (K-split),
// partial sums written to C + blockIdx.x * sKout.

static constexpr int BK   = 32;
static constexpr int LDT  = 40;   // bf16 elems per smem row (80B)
static constexpr int NSTG = 2;

__device__ __forceinline__ void cp16(void* dst, const void* src, int srcbytes) {
    unsigned int d = (unsigned int)__cvta_generic_to_shared(dst);
    asm volatile("cp.async.cg.shared.global [%0], [%1], 16, %2;\n"
                 :: "r"(d), "l"(src), "r"(srcbytes));
}
__device__ __forceinline__ void cp_commit() {
    asm volatile("cp.async.commit_group;\n");
}
template<int Nleft>
__device__ __forceinline__ void cp_wait() {
    asm volatile("cp.async.wait_group %0;\n" :: "n"(Nleft));
}

template<int NJ, bool GUARD, bool OUTSPLIT>
__global__ void __launch_bounds__(256)
gemm_bf(const bf16* __restrict__ Ah, const bf16* __restrict__ Al, long sA,
        const bf16* __restrict__ Bh, const bf16* __restrict__ Bl, long sB,
        float* __restrict__ C, bf16* __restrict__ Chi, bf16* __restrict__ Clo, long sC,
        const float* __restrict__ bias,
        int M, int N, int K, long sKout)
{
    constexpr int BN  = 64 * NJ;
    constexpr int A_T = 128 * LDT;           // bf16 elems per A tile (5120)
    constexpr int B_T = BN * LDT;
    constexpr int STG = 2 * A_T + 2 * B_T;   // hi + lo
    constexpr int LDCs = BN + 4;
    extern __shared__ bf16 smb[];
    float* smf = reinterpret_cast<float*>(smb);   // epilogue/bias alias

    const int t = threadIdx.x;
    const int wid = t >> 5;
    const int wm = wid & 1;        // 0..1  (64-row slab)
    const int wn = wid >> 1;       // 0..3  (16*NJ-col slab)
    const long m0 = (long)blockIdx.y * 128;
    const int  n0 = GUARD ? 0 : blockIdx.x * BN;
    Ah += (long)blockIdx.z * sA;  Al += (long)blockIdx.z * sA;
    Bh += (long)blockIdx.z * sB;  Bl += (long)blockIdx.z * sB;
    if (C)   C   += (long)blockIdx.z * sC;
    if (Chi) { Chi += (long)blockIdx.z * sC; Clo += (long)blockIdx.z * sC; }
    // GUARD: blockIdx.x = K-slice index
    if (GUARD) {
        int kb = blockIdx.x * K;          // K = per-slice length
        Ah += kb; Al += kb; Bh += kb; Bl += kb;
        C  += (long)blockIdx.x * sKout;
    }

    const int r4 = t >> 2;
    const int c4 = (t & 3) * 8;
    // full row stride in bf16 elems: GUARD kernels stride by total K (2 slices)
    const long KR = GUARD ? (long)K * 2 : (long)K;
    const bf16* Ahg0 = Ah + (m0 + r4) * KR + c4;
    const bf16* Alg0 = Al + (m0 + r4) * KR + c4;
    const bf16* Ahg1 = Ahg0 + 64 * KR;
    const bf16* Alg1 = Alg0 + 64 * KR;
    const int bn0 = n0 + r4;
    const int bn1 = n0 + r4 + 64;
    const int bnc0 = GUARD ? (bn0 < N ? bn0 : 0) : bn0;
    const bf16* Bhg0 = Bh + (long)bnc0 * KR + c4;
    const bf16* Blg0 = Bl + (long)bnc0 * KR + c4;
    const bf16* Bhg1 = Bh + (long)bn1 * KR + c4;   // only used when NJ==2 (no guard)
    const bf16* Blg1 = Bl + (long)bn1 * KR + c4;
    const int  bb0 = (!GUARD || bn0 < N) ? 16 : 0;

    wmma::fragment<wmma::accumulator, 16, 16, 16, float> acc[4][NJ];

    // ---- bias -> accumulator init ----
    if (bias) {
        if (t < BN) {
            float v = (!GUARD || (n0 + t) < N) ? bias[n0 + t] : 0.f;
#pragma unroll
            for (int r = 0; r < 16; r++) smf[r * LDCs + t] = v;
        }
        __syncthreads();
        wmma::fragment<wmma::accumulator, 16, 16, 16, float> bf;
#pragma unroll
        for (int j = 0; j < NJ; j++) {
            wmma::load_matrix_sync(bf, smf + wn * 16 * NJ + j * 16, LDCs, wmma::mem_row_major);
#pragma unroll
            for (int i = 0; i < 4; i++)
#pragma unroll
                for (int e = 0; e < bf.num_elements; e++) acc[i][j].x[e] = bf.x[e];
        }
        __syncthreads();
    } else {
#pragma unroll
        for (int i = 0; i < 4; i++)
#pragma unroll
            for (int j = 0; j < NJ; j++) wmma::fill_fragment(acc[i][j], 0.f);
    }

    auto issue = [&](int s, int k) {
        bf16* st = smb + (size_t)s * STG;
        cp16(st + r4 * LDT + c4,               Ahg0 + k, 16);
        cp16(st + (r4 + 64) * LDT + c4,        Ahg1 + k, 16);
        cp16(st + A_T + r4 * LDT + c4,         Alg0 + k, 16);
        cp16(st + A_T + (r4 + 64) * LDT + c4,  Alg1 + k, 16);
        bf16* bs = st + 2 * A_T;
        cp16(bs + r4 * LDT + c4,       Bhg0 + k, bb0);
        cp16(bs + B_T + r4 * LDT + c4, Blg0 + k, bb0);
        if (NJ == 2) {
            cp16(bs + (r4 + 64) * LDT + c4,       Bhg1 + k, 16);
            cp16(bs + B_T + (r4 + 64) * LDT + c4, Blg1 + k, 16);
        }
    };

    issue(0, 0);
    cp_commit();

    int s = 0;
    for (int k0 = 0; k0 < K; k0 += BK) {
        cp_wait<0>();
        __syncthreads();
        if (k0 + BK < K) issue(s ^ 1, k0 + BK);
        cp_commit();

        bf16* st = smb + (size_t)s * STG;
#pragma unroll
        for (int kk = 0; kk < BK; kk += 16) {
            wmma::fragment<wmma::matrix_a, 16, 16, 16, bf16, wmma::row_major> ah[4], al[4];
            wmma::fragment<wmma::matrix_b, 16, 16, 16, bf16, wmma::col_major> bh[NJ], bl[NJ];
#pragma unroll
            for (int i = 0; i < 4; i++) {
                int r = wm * 64 + i * 16;
                wmma::load_matrix_sync(ah[i], st + r * LDT + kk, LDT);
                wmma::load_matrix_sync(al[i], st + A_T + r * LDT + kk, LDT);
            }
#pragma unroll
            for (int j = 0; j < NJ; j++) {
                int c = wn * 16 * NJ + j * 16;
                wmma::load_matrix_sync(bh[j], st + 2 * A_T + c * LDT + kk, LDT);
                wmma::load_matrix_sync(bl[j], st + 2 * A_T + B_T + c * LDT + kk, LDT);
            }
#pragma unroll
            for (int i = 0; i < 4; i++)
#pragma unroll
                for (int j = 0; j < NJ; j++) {
                    wmma::mma_sync(acc[i][j], al[i], bh[j], acc[i][j]);
                    wmma::mma_sync(acc[i][j], ah[i], bl[j], acc[i][j]);
                    wmma::mma_sync(acc[i][j], ah[i], bh[j], acc[i][j]);
                }
        }
        s ^= 1;
    }

    // ---- epilogue ----
    if (OUTSPLIT) {
        __syncthreads();
#pragma unroll
        for (int i = 0; i < 4; i++)
#pragma unroll
            for (int j = 0; j < NJ; j++)
                wmma::store_matrix_sync(smf + (wm * 64 + i * 16) * LDCs + wn * 16 * NJ + j * 16,
                                        acc[i][j], LDCs, wmma::mem_row_major);
        __syncthreads();
        for (int e = t; e < 128 * BN; e += 256) {
            int r = e / BN, cn = e % BN;
            float v = smf[r * LDCs + cn];
            bf16 h = __float2bfloat16(v);
            long o = (m0 + r) * (long)N + n0 + cn;
            Chi[o] = h;
            Clo[o] = __float2bfloat16(v - __bfloat162float(h));
        }
    } else if (!GUARD) {
#pragma unroll
        for (int i = 0; i < 4; i++)
#pragma unroll
            for (int j = 0; j < NJ; j++)
                wmma::store_matrix_sync(
                    C + (m0 + wm * 64 + i * 16) * (long)N + n0 + wn * 16 * NJ + j * 16,
                    acc[i][j], N, wmma::mem_row_major);
    } else {
        __syncthreads();
        for (int half = 0; half < 2; half++) {
            if (wm == half) {
#pragma unroll
                for (int i = 0; i < 4; i++)
#pragma unroll
                    for (int j = 0; j < NJ; j++)
                        wmma::store_matrix_sync(smf + (i * 16) * LDCs + wn * 16 * NJ + j * 16,
                                                acc[i][j], LDCs, wmma::mem_row_major);
            }
            __syncthreads();
            for (int e = t; e < 64 * BN; e += 256) {
                int r = e / BN, cn = e % BN;
                int n = n0 + cn;
                if (n < N)
                    C[(m0 + half * 64 + r) * (long)N + n] = smf[r * LDCs + cn];
            }
            __syncthreads();
        }
    }
}

// ------- depthwise causal conv + silu -> u hi/lo; 8 consecutive d per thread ---
// One l per thread: taps are 4 packed rows of 8 floats; stores are 2x 16B.
__global__ void conv_silu_kernel(const float* __restrict__ cw, const float* __restrict__ cb)
{
    const float L2E = 1.4426950408889634f;
    int t = blockIdx.x * blockDim.x + threadIdx.x;   // 2*B*L*(DI/8) = 2^20
    int dq  = t & 63;                // d-group: d0 = dq*8
    int l   = (t >> 6) & (L_ - 1);
    int b   = (t >> 17) & 3;
    int dir = (t >> 19) & 1;
    int d0  = dq * 8;
    const float* xi = g_xz + (size_t)dir * BL * 2 * DI;   // xi = first DI cols

    // weights for 8 channels: 32 contiguous floats at (dir*DI+d0)*4
    float4 wq[8];
    {
        const float4* wp = (const float4*)(cw + (size_t)(dir * DI + d0) * 4);
#pragma unroll
        for (int j = 0; j < 8; j++) wq[j] = wp[j];
    }
    float4 bva = *(const float4*)(cb + dir * DI + d0);
    float4 bvb = *(const float4*)(cb + dir * DI + d0 + 4);
    float bv[8] = {bva.x, bva.y, bva.z, bva.w, bvb.x, bvb.y, bvb.z, bvb.w};

    // 4 tap rows (dir0: l-3..l ; dir1: l..l+3), 8 floats each
    float rowv[4][8];
#pragma unroll
    for (int k = 0; k < 4; k++) {
        int ll = dir ? (l + k) : (l - 3 + k);
        if (ll >= 0 && ll < L_) {
            const float4* rp = (const float4*)(xi + ((size_t)b * L_ + ll) * (2 * DI) + d0);
            float4 a = rp[0], c = rp[1];
            rowv[k][0] = a.x; rowv[k][1] = a.y; rowv[k][2] = a.z; rowv[k][3] = a.w;
            rowv[k][4] = c.x; rowv[k][5] = c.y; rowv[k][6] = c.z; rowv[k][7] = c.w;
        } else {
#pragma unroll
            for (int j = 0; j < 8; j++) rowv[k][j] = 0.f;
        }
    }

    bf16 hb[8], lb[8];
#pragma unroll
    for (int j = 0; j < 8; j++) {
        float acc = bv[j];
        if (dir == 0) {
            // out[l] = sum_k w[k] * xi[l-3+k] ; rowv[k] holds xi[l-3+k]
            acc = fmaf(wq[j].x, rowv[0][j], acc);
            acc = fmaf(wq[j].y, rowv[1][j], acc);
            acc = fmaf(wq[j].z, rowv[2][j], acc);
            acc = fmaf(wq[j].w, rowv[3][j], acc);
        } else {
            // out[l] = sum_k w[k] * xi[l+3-k] ; rowv[i] holds xi[l+i] -> w[3-i]
            acc = fmaf(wq[j].w, rowv[0][j], acc);
            acc = fmaf(wq[j].z, rowv[1][j], acc);
            acc = fmaf(wq[j].y, rowv[2][j], acc);
            acc = fmaf(wq[j].x, rowv[3][j], acc);
        }
        float uvv = acc * rcpf(1.f + ex2f(-acc * L2E));   // silu via rcp.approx
        bf16 h = __float2bfloat16(uvv);
        hb[j] = h;
        lb[j] = __float2bfloat16(uvv - __bfloat162float(h));
    }
    size_t o = (size_t)dir * BL * DI + ((size_t)b * L_ + l) * DI + d0;
    *(uint4*)(g_uh + o) = *(const uint4*)hb;
    *(uint4*)(g_ul + o) = *(const uint4*)lb;
}

// ---------------- chunked selective scan, pass 1 ------------------------------
// dt fused; f32x2-packed recurrences; dbc K-slabs summed into smem per chunk.
__global__ void __launch_bounds__(128)
scan1_kernel(const float* __restrict__ A_log, const float* __restrict__ Dp,
             const float* __restrict__ dt_w, const float* __restrict__ dt_b)
{
    __shared__ float srow[LC * 48];       // 32 rows x 48 floats = 6 KB

    int bid = blockIdx.x;                 // 2048 = 2*4*64*4
    int dq  = bid & 3;
    int c   = (bid >> 2) & (NCH - 1);
    int b   = (bid >> 8) & 3;
    int dir = bid >> 10;
    int d   = dq * 128 + threadIdx.x;

    const bf16*  uhp = g_uh  + (size_t)dir * BL * DI;
    const bf16*  ulp = g_ul  + (size_t)dir * BL * DI;
    const float* zp  = g_xz  + (size_t)dir * BL * 2 * DI + DI;   // z half
    const float* dbp = g_dbc + (size_t)dir * BL * 48;            // K-slab 0

    // cooperative load of this chunk's 32 dbc rows, summing the two K-slabs
    {
        int l_lo = dir ? (L_ - LC - c * LC) : c * LC;
        const float4* g0 = (const float4*)(dbp + ((size_t)b * L_ + l_lo) * 48);
        const float4* g1 = (const float4*)((const float*)g0 + (size_t)2 * BL * 48);
        float4* s4 = (float4*)srow;
#pragma unroll
        for (int i = 0; i < 3; i++) {
            float4 a = g0[threadIdx.x + i * 128];
            float4 bq = g1[threadIdx.x + i * 128];
            s4[threadIdx.x + i * 128] =
                make_float4(a.x + bq.x, a.y + bq.y, a.z + bq.z, a.w + bq.w);
        }
    }
    __syncthreads();

    const float L2E = 1.4426950408889634f;
    const float LN2 = 0.6931471805599453f;
    float2 a2[NS / 2];
#pragma unroll
    for (int i = 0; i < NS / 2; i++) {
        const float* ap = A_log + (size_t)(dir * DI + d) * NS + 2 * i;
        a2[i] = make_float2(-__expf(ap[0]) * L2E, -__expf(ap[1]) * L2E);
    }
    const float Dv = Dp[dir * DI + d];

    float2 w2[RK / 2];
    {
        const float* wr = dt_w + (size_t)(dir * DI + d) * RK;
#pragma unroll
        for (int i = 0; i < RK / 2; i++) w2[i] = make_float2(wr[2 * i], wr[2 * i + 1]);
    }
    const float bb = dt_b[dir * DI + d];

    float2 h2[NS / 2], pp2[NS / 2], Kk2[NS / 2];
#pragma unroll
    for (int i = 0; i < NS / 2; i++) {
        h2[i] = make_float2(0.f, 0.f);
        pp2[i] = make_float2(1.f, 1.f);
        Kk2[i] = make_float2(0.f, 0.f);
    }
    float accl = 0.f;

    for (int j = 0; j < LC; j++) {
        int ss = c * LC + j;
        int l = dir ? (L_ - 1 - ss) : ss;
        size_t base = (size_t)b * L_ + l;
        float uv = __bfloat162float(uhp[base * DI + d]) + __bfloat162float(ulp[base * DI + d]);
        float zv = zp[base * 2 * DI + d];
        float gate = zv * rcpf(1.f + ex2f(-zv * L2E));

        int jr = dir ? (LC - 1 - j) : j;
        const float4* rr = (const float4*)(srow + jr * 48);
        float4 p0 = rr[0], p1 = rr[1], p2 = rr[2], p3 = rr[3];   // dt_lr
        float2 s2 = make_float2(bb, 0.f);
        s2 = fma2(make_float2(p0.x, p0.y), w2[0], s2);
        s2 = fma2(make_float2(p0.z, p0.w), w2[1], s2);
        s2 = fma2(make_float2(p1.x, p1.y), w2[2], s2);
        s2 = fma2(make_float2(p1.z, p1.w), w2[3], s2);
        s2 = fma2(make_float2(p2.x, p2.y), w2[4], s2);
        s2 = fma2(make_float2(p2.z, p2.w), w2[5], s2);
        s2 = fma2(make_float2(p3.x, p3.y), w2[6], s2);
        s2 = fma2(make_float2(p3.z, p3.w), w2[7], s2);
        float sdt = s2.x + s2.y;
        float dtv = (sdt > 15.f) ? sdt : LN2 * lg2f(1.f + ex2f(sdt * L2E));
        float x = dtv * uv;

        float4 q0 = rr[4], q1 = rr[5], q2 = rr[6], q3 = rr[7];   // B
        float4 q4 = rr[8], q5 = rr[9], q6 = rr[10], q7 = rr[11]; // C
        float2 Bv[8] = {{q0.x, q0.y}, {q0.z, q0.w}, {q1.x, q1.y}, {q1.z, q1.w},
                        {q2.x, q2.y}, {q2.z, q2.w}, {q3.x, q3.y}, {q3.z, q3.w}};
        float2 Cv[8] = {{q4.x, q4.y}, {q4.z, q4.w}, {q5.x, q5.y}, {q5.z, q5.w},
                        {q6.x, q6.y}, {q6.z, q6.w}, {q7.x, q7.y}, {q7.z, q7.w}};

        float2 dt2 = make_float2(dtv, dtv);
        float2 x2  = make_float2(x, x);
        float2 g2  = make_float2(gate, gate);
        float2 y2  = make_float2(0.f, 0.f);
#pragma unroll
        for (int i = 0; i < NS / 2; i++) {
            float2 m = mul2(dt2, a2[i]);
            float2 dA = make_float2(ex2f(m.x), ex2f(m.y));
            h2[i]  = fma2(dA, h2[i], mul2(x2, Bv[i]));
            pp2[i] = mul2(pp2[i], dA);
            y2     = fma2(h2[i], Cv[i], y2);
            Kk2[i] = fma2(mul2(g2, Cv[i]), pp2[i], Kk2[i]);
        }
        accl = fmaf(gate, fmaf(uv, Dv, y2.x + y2.y), accl);
    }

    size_t r = (((size_t)dir * NCH + c) * B_ + b) * DI + d;
    g_al[r] = accl;
#pragma unroll
    for (int i = 0; i < NS / 2; i++) {
        *(float2*)&g_S [r * NS + 2 * i] = h2[i];
        *(float2*)&g_P [r * NS + 2 * i] = pp2[i];
        *(float2*)&g_Kc[r * NS + 2 * i] = Kk2[i];
    }
}

// ---------------- scan combine: 16 lanes per (dir,b,d), shuffle-reduce --------
__global__ void scan2_kernel()
{
    int t = blockIdx.x * blockDim.x + threadIdx.x;   // 65536
    int n   = t & 15;
    int idx = t >> 4;        // 0..4095 = dir*2048 + b*512 + d
    int dir = idx >> 11;
    int b   = (idx >> 9) & 3;
    int d   = idx & (DI - 1);
    float hin = 0.f, acc = 0.f;
    for (int c = 0; c < NCH; c++) {
        size_t r = (((size_t)dir * NCH + c) * B_ + b) * DI + d;
        if (n == 0) acc += g_al[r];
        acc = fmaf(hin, g_Kc[r * NS + n], acc);
        hin = fmaf(g_P[r * NS + n], hin, g_S[r * NS + n]);
    }
#pragma unroll
    for (int o = 8; o; o >>= 1) acc += __shfl_down_sync(0xffffffffu, acc, o, 16);
    if (n == 0) g_pool[idx] = acc;
}

// ---------------- head: pooled @ out_w^T (per dir) -> embd --------------------
__global__ void head1_kernel(const float* __restrict__ out_w)
{
    int idx = blockIdx.x * blockDim.x + threadIdx.x;   // B * 512 = 2048
    if (idx >= B_ * 2 * HID) return;
    int b = idx >> 9;
    int cf = idx & 511;
    int dir = cf >> 8;
    int cc = cf & (HID - 1);
    const float* pr = g_pool + dir * B_ * DI + b * DI;
    const float* wr = out_w + ((size_t)dir * HID + cc) * DI;
    float s = 0.f;
#pragma unroll 8
    for (int k = 0; k < DI; k++) s = fmaf(pr[k], wr[k], s);
    g_embd[b * 512 + cf] = s * (1.f / (float)L_);
}

// ---------------- head: embd @ op_w^T + op_b ----------------------------------
__global__ void head2_kernel(const float* __restrict__ op_w, const float* __restrict__ op_b,
                             float* __restrict__ out)
{
    int idx = blockIdx.x * blockDim.x + threadIdx.x;   // B * 256 = 1024
    if (idx >= B_ * HID) return;
    int b = idx >> 8;
    int m = idx & (HID - 1);
    const float* e = g_embd + b * 512;
    const float* w = op_w + (size_t)m * 512;
    float s = op_b[m];
#pragma unroll 8
    for (int c = 0; c < 512; c++) s = fmaf(e[c], w[c], s);
    out[b * HID + m] = s;
}

// ------------------------------------------------------------------------------
extern "C" void kernel_launch(void* const* d_in, const int* in_sizes, int n_in,
                              void* d_out, int out_size)
{
    const float* x      = (const float*)d_in[0];
    const float* ip_w   = (const float*)d_in[1];
    const float* ip_b   = (const float*)d_in[2];
    const float* in_w   = (const float*)d_in[3];
    const float* conv_w = (const float*)d_in[4];
    const float* conv_b = (const float*)d_in[5];
    const float* xproj_w= (const float*)d_in[6];
    const float* dt_w   = (const float*)d_in[7];
    const float* dt_b   = (const float*)d_in[8];
    const float* A_log  = (const float*)d_in[9];
    const float* Dp     = (const float*)d_in[10];
    const float* out_w  = (const float*)d_in[11];
    const float* op_w   = (const float*)d_in[12];
    const float* op_b   = (const float*)d_in[13];
    float* out = (float*)d_out;

    float *pxz, *pdbc;
    bf16 *pxh, *pxl, *phh, *phl, *puh, *pul, *pipwh, *pipwl, *pinwh, *pinwl, *pxpwh, *pxpwl;
    cudaGetSymbolAddress((void**)&pxz,   g_xz);
    cudaGetSymbolAddress((void**)&pdbc,  g_dbc);
    cudaGetSymbolAddress((void**)&pxh,   g_xh);
    cudaGetSymbolAddress((void**)&pxl,   g_xl);
    cudaGetSymbolAddress((void**)&phh,   g_hh);
    cudaGetSymbolAddress((void**)&phl,   g_hl);
    cudaGetSymbolAddress((void**)&puh,   g_uh);
    cudaGetSymbolAddress((void**)&pul,   g_ul);
    cudaGetSymbolAddress((void**)&pipwh, g_ipwh);
    cudaGetSymbolAddress((void**)&pipwl, g_ipwl);
    cudaGetSymbolAddress((void**)&pinwh, g_inwh);
    cudaGetSymbolAddress((void**)&pinwl, g_inwl);
    cudaGetSymbolAddress((void**)&pxpwh, g_xpwh);
    cudaGetSymbolAddress((void**)&pxpwl, g_xpwl);

    const int smem1 = NSTG * (2 * 128 * LDT + 2 * 64 * LDT) * (int)sizeof(bf16);   // 61440
    const int smem2 = NSTG * (2 * 128 * LDT + 2 * 128 * LDT) * (int)sizeof(bf16);  // 81920
    cudaFuncSetAttribute(gemm_bf<2, false, true>,  cudaFuncAttributeMaxDynamicSharedMemorySize, smem2);
    cudaFuncSetAttribute(gemm_bf<2, false, false>, cudaFuncAttributeMaxDynamicSharedMemorySize, smem2);
    cudaFuncSetAttribute(gemm_bf<1, true, false>,  cudaFuncAttributeMaxDynamicSharedMemorySize, smem1);

    dim3 blk(256);
    const int n0 = BL * 512, n1 = HID * 512, n2 = 2 * 1024 * HID, n3 = 2 * 48 * 512;

    // 1) split x + all weights -> bf16 hi/lo (ONE launch, packed stores)
    split_all<<<((n0 + n1 + n2 + n3) / 8 + 255) / 256, 256>>>(
        x, pxh, pxl, n0,
        ip_w, pipwh, pipwl, n1,
        in_w, pinwh, pinwl, n2,
        xproj_w, pxpwh, pxpwl, n3);
    // 2) h = x @ ip_w^T + ip_b -> bf16 hi/lo directly   [8192,512]x[256,512], BN=128
    gemm_bf<2, false, true><<<dim3(HID / 128, BL / 128, 1), blk, smem2>>>(
        pxh, pxl, 0, pipwh, pipwl, 0, nullptr, phh, phl, 0, ip_b, BL, HID, 512, 0);
    // 3) xz_dir = h @ in_w[dir]^T   [8192,256]x[1024,256] -> [8192,1024] x2
    gemm_bf<2, false, false><<<dim3(1024 / 128, BL / 128, 2), blk, smem2>>>(
        phh, phl, 0, pinwh, pinwl, (long)1024 * HID, pxz, nullptr, nullptr, (long)BL * 1024,
        nullptr, BL, 1024, HID, 0);
    // 4) u = silu(depthwise causal conv(xi) + cb), 8 d's/thread, packed stores (PROFILED)
    conv_silu_kernel<<<(2 * BL * DI / 8) / 256, 256>>>(conv_w, conv_b);
    // 5) dbc_partial[ks] = u @ xproj_w[dir][:, ks*256:(ks+1)*256]^T  (K-split x2)
    gemm_bf<1, true, false><<<dim3(2, BL / 128, 2), blk, smem1>>>(
        puh, pul, (long)BL * DI, pxpwh, pxpwl, (long)48 * 512, pdbc, nullptr, nullptr,
        (long)BL * 48, nullptr, BL, 48, 256, (long)2 * BL * 48);
    // 6) chunked scan pass 1 (dt fused; K-slabs summed in smem; f32x2 recurrences)
    scan1_kernel<<<2048, 128>>>(A_log, Dp, dt_w, dt_b);
    // 7) chunk combine -> pooled sums
    scan2_kernel<<<256, 256>>>();
    // 8) pooled @ out_w^T (mean folded), concat dirs -> embd
    head1_kernel<<<8, 256>>>(out_w);
    // 9) embd @ op_w^T + op_b -> out
    head2_kernel<<<4, 256>>>(op_w, op_b, out);
}

// round 17
// speedup vs baseline: 1.0649x; 1.0649x over previous
#include <cuda_runtime.h>
#include <cuda_bf16.h>
#include <cstdint>
#include <math.h>
#include <mma.h>

using namespace nvcuda;
typedef __nv_bfloat16 bf16;

static constexpr int B_  = 4;
static constexpr int L_  = 2048;
static constexpr int HID = 256;   // hidden after input proj
static constexpr int DI  = 512;   // d_inner
static constexpr int NS  = 16;    // d_state
static constexpr int RK  = 16;    // dt_rank
static constexpr int NCH = 64;    // chunks
static constexpr int LC  = 32;    // chunk length (NCH*LC == L_)
static constexpr int BL  = B_ * L_;   // 8192

// ---------------- scratch (device globals; no allocations allowed) -------------
__device__ __align__(256) float g_xz  [2 * BL * 2 * DI];    // per-dir xz (xi | z)
__device__ __align__(256) float g_dbc [2 * 2 * BL * 48];    // x-proj out, 2 K-slabs
__device__ __align__(256) float g_S   [2 * NCH * B_ * DI * NS];
__device__ __align__(256) float g_P   [2 * NCH * B_ * DI * NS];
__device__ __align__(256) float g_Kc  [2 * NCH * B_ * DI * NS];
__device__ __align__(256) float g_al  [2 * NCH * B_ * DI];
__device__ __align__(256) float g_pool[2 * B_ * DI];
__device__ __align__(256) float g_embd[B_ * 2 * HID];
// bf16 hi/lo split operands
__device__ __align__(256) bf16 g_xh  [BL * 512],        g_xl  [BL * 512];
__device__ __align__(256) bf16 g_hh  [BL * HID],        g_hl  [BL * HID];
__device__ __align__(256) bf16 g_uh  [2 * BL * DI],     g_ul  [2 * BL * DI];
__device__ __align__(256) bf16 g_ipwh[HID * 512],       g_ipwl[HID * 512];
__device__ __align__(256) bf16 g_inwh[2 * 1024 * HID],  g_inwl[2 * 1024 * HID];
__device__ __align__(256) bf16 g_xpwh[2 * 48 * 512],    g_xpwl[2 * 48 * 512];

// ---------------- packed f32x2 + fast-transcendental helpers -------------------
__device__ __forceinline__ float2 fma2(float2 a, float2 b, float2 c) {
    float2 r;
    asm("fma.rn.f32x2 %0, %1, %2, %3;"
        : "=l"(*reinterpret_cast<unsigned long long*>(&r))
        : "l"(*reinterpret_cast<unsigned long long*>(&a)),
          "l"(*reinterpret_cast<unsigned long long*>(&b)),
          "l"(*reinterpret_cast<unsigned long long*>(&c)));
    return r;
}
__device__ __forceinline__ float2 mul2(float2 a, float2 b) {
    float2 r;
    asm("mul.rn.f32x2 %0, %1, %2;"
        : "=l"(*reinterpret_cast<unsigned long long*>(&r))
        : "l"(*reinterpret_cast<unsigned long long*>(&a)),
          "l"(*reinterpret_cast<unsigned long long*>(&b)));
    return r;
}
__device__ __forceinline__ float ex2f(float x) {
    float r; asm("ex2.approx.f32 %0, %1;" : "=f"(r) : "f"(x)); return r;
}
__device__ __forceinline__ float lg2f(float x) {
    float r; asm("lg2.approx.f32 %0, %1;" : "=f"(r) : "f"(x)); return r;
}
__device__ __forceinline__ float rcpf(float x) {
    float r; asm("rcp.approx.f32 %0, %1;" : "=f"(r) : "f"(x)); return r;
}

// ------- fp32 -> bf16 (hi, lo) splits: 8 elems/thread, packed uint4 stores -----
__global__ void split_all(const float* __restrict__ w0, bf16* __restrict__ h0, bf16* __restrict__ l0, int n0,
                          const float* __restrict__ w1, bf16* __restrict__ h1, bf16* __restrict__ l1, int n1,
                          const float* __restrict__ w2, bf16* __restrict__ h2, bf16* __restrict__ l2, int n2,
                          const float* __restrict__ w3, bf16* __restrict__ h3, bf16* __restrict__ l3, int n3)
{
    int i = (blockIdx.x * blockDim.x + threadIdx.x) * 8;
    const float* s; bf16 *ph, *pl; int off;
    if (i < n0)                     { s = w0; ph = h0; pl = l0; off = i; }
    else if (i < n0 + n1)           { s = w1; ph = h1; pl = l1; off = i - n0; }
    else if (i < n0 + n1 + n2)      { s = w2; ph = h2; pl = l2; off = i - n0 - n1; }
    else if (i < n0 + n1 + n2 + n3) { s = w3; ph = h3; pl = l3; off = i - n0 - n1 - n2; }
    else return;
    float4 va = *(const float4*)(s + off);
    float4 vb = *(const float4*)(s + off + 4);
    float vv[8] = {va.x, va.y, va.z, va.w, vb.x, vb.y, vb.z, vb.w};
    bf16 hb[8], lb[8];
#pragma unroll
    for (int j = 0; j < 8; j++) {
        bf16 h = __float2bfloat16(vv[j]);
        hb[j] = h;
        lb[j] = __float2bfloat16(vv[j] - __bfloat162float(h));
    }
    *(uint4*)(ph + off) = *(const uint4*)hb;
    *(uint4*)(pl + off) = *(const uint4*)lb;
}

// =================== bf16 tensor-core GEMM (3-term split), BK=32, 2-stage ======
// C[M,N] = A[M,K] @ W[N,K]^T (+bias), operands as bf16 (hi, lo) pairs.
// Product al*bh + ah*bl + ah*bh -> ~2^-17 relative error; fp32 accumulate.
// Block tile 128 x (64*NJ) x 32; 256 threads = 8 warps in 2(m) x 4(n).
// GUARD mode: N<=64 single N-tile; blockIdx.x selects a K-slice (K-split),
// partial sums written to C + blockIdx.x * sKout.

static constexpr int BK   = 32;
static constexpr int LDT  = 40;   // bf16 elems per smem row (80B)
static constexpr int NSTG = 2;

__device__ __forceinline__ void cp16(void* dst, const void* src, int srcbytes) {
    unsigned int d = (unsigned int)__cvta_generic_to_shared(dst);
    asm volatile("cp.async.cg.shared.global [%0], [%1], 16, %2;\n"
                 :: "r"(d), "l"(src), "r"(srcbytes));
}
__device__ __forceinline__ void cp_commit() {
    asm volatile("cp.async.commit_group;\n");
}
template<int Nleft>
__device__ __forceinline__ void cp_wait() {
    asm volatile("cp.async.wait_group %0;\n" :: "n"(Nleft));
}

template<int NJ, bool GUARD, bool OUTSPLIT>
__global__ void __launch_bounds__(256)
gemm_bf(const bf16* __restrict__ Ah, const bf16* __restrict__ Al, long sA,
        const bf16* __restrict__ Bh, const bf16* __restrict__ Bl, long sB,
        float* __restrict__ C, bf16* __restrict__ Chi, bf16* __restrict__ Clo, long sC,
        const float* __restrict__ bias,
        int M, int N, int K, long sKout)
{
    constexpr int BN  = 64 * NJ;
    constexpr int A_T = 128 * LDT;           // bf16 elems per A tile (5120)
    constexpr int B_T = BN * LDT;
    constexpr int STG = 2 * A_T + 2 * B_T;   // hi + lo
    constexpr int LDCs = BN + 4;
    extern __shared__ bf16 smb[];
    float* smf = reinterpret_cast<float*>(smb);   // epilogue/bias alias

    const int t = threadIdx.x;
    const int wid = t >> 5;
    const int wm = wid & 1;        // 0..1  (64-row slab)
    const int wn = wid >> 1;       // 0..3  (16*NJ-col slab)
    const long m0 = (long)blockIdx.y * 128;
    const int  n0 = GUARD ? 0 : blockIdx.x * BN;
    Ah += (long)blockIdx.z * sA;  Al += (long)blockIdx.z * sA;
    Bh += (long)blockIdx.z * sB;  Bl += (long)blockIdx.z * sB;
    if (C)   C   += (long)blockIdx.z * sC;
    if (Chi) { Chi += (long)blockIdx.z * sC; Clo += (long)blockIdx.z * sC; }
    // GUARD: blockIdx.x = K-slice index
    if (GUARD) {
        int kb = blockIdx.x * K;          // K = per-slice length
        Ah += kb; Al += kb; Bh += kb; Bl += kb;
        C  += (long)blockIdx.x * sKout;
    }

    const int r4 = t >> 2;
    const int c4 = (t & 3) * 8;
    // full row stride in bf16 elems: GUARD kernels stride by total K (2 slices)
    const long KR = GUARD ? (long)K * 2 : (long)K;
    const bf16* Ahg0 = Ah + (m0 + r4) * KR + c4;
    const bf16* Alg0 = Al + (m0 + r4) * KR + c4;
    const bf16* Ahg1 = Ahg0 + 64 * KR;
    const bf16* Alg1 = Alg0 + 64 * KR;
    const int bn0 = n0 + r4;
    const int bn1 = n0 + r4 + 64;
    const int bnc0 = GUARD ? (bn0 < N ? bn0 : 0) : bn0;
    const bf16* Bhg0 = Bh + (long)bnc0 * KR + c4;
    const bf16* Blg0 = Bl + (long)bnc0 * KR + c4;
    const bf16* Bhg1 = Bh + (long)bn1 * KR + c4;   // only used when NJ==2 (no guard)
    const bf16* Blg1 = Bl + (long)bn1 * KR + c4;
    const int  bb0 = (!GUARD || bn0 < N) ? 16 : 0;

    wmma::fragment<wmma::accumulator, 16, 16, 16, float> acc[4][NJ];

    // ---- bias -> accumulator init ----
    if (bias) {
        if (t < BN) {
            float v = (!GUARD || (n0 + t) < N) ? bias[n0 + t] : 0.f;
#pragma unroll
            for (int r = 0; r < 16; r++) smf[r * LDCs + t] = v;
        }
        __syncthreads();
        wmma::fragment<wmma::accumulator, 16, 16, 16, float> bf;
#pragma unroll
        for (int j = 0; j < NJ; j++) {
            wmma::load_matrix_sync(bf, smf + wn * 16 * NJ + j * 16, LDCs, wmma::mem_row_major);
#pragma unroll
            for (int i = 0; i < 4; i++)
#pragma unroll
                for (int e = 0; e < bf.num_elements; e++) acc[i][j].x[e] = bf.x[e];
        }
        __syncthreads();
    } else {
#pragma unroll
        for (int i = 0; i < 4; i++)
#pragma unroll
            for (int j = 0; j < NJ; j++) wmma::fill_fragment(acc[i][j], 0.f);
    }

    auto issue = [&](int s, int k) {
        bf16* st = smb + (size_t)s * STG;
        cp16(st + r4 * LDT + c4,               Ahg0 + k, 16);
        cp16(st + (r4 + 64) * LDT + c4,        Ahg1 + k, 16);
        cp16(st + A_T + r4 * LDT + c4,         Alg0 + k, 16);
        cp16(st + A_T + (r4 + 64) * LDT + c4,  Alg1 + k, 16);
        bf16* bs = st + 2 * A_T;
        cp16(bs + r4 * LDT + c4,       Bhg0 + k, bb0);
        cp16(bs + B_T + r4 * LDT + c4, Blg0 + k, bb0);
        if (NJ == 2) {
            cp16(bs + (r4 + 64) * LDT + c4,       Bhg1 + k, 16);
            cp16(bs + B_T + (r4 + 64) * LDT + c4, Blg1 + k, 16);
        }
    };

    issue(0, 0);
    cp_commit();

    int s = 0;
    for (int k0 = 0; k0 < K; k0 += BK) {
        cp_wait<0>();
        __syncthreads();
        if (k0 + BK < K) issue(s ^ 1, k0 + BK);
        cp_commit();

        bf16* st = smb + (size_t)s * STG;
#pragma unroll
        for (int kk = 0; kk < BK; kk += 16) {
            wmma::fragment<wmma::matrix_a, 16, 16, 16, bf16, wmma::row_major> ah[4], al[4];
            wmma::fragment<wmma::matrix_b, 16, 16, 16, bf16, wmma::col_major> bh[NJ], bl[NJ];
#pragma unroll
            for (int i = 0; i < 4; i++) {
                int r = wm * 64 + i * 16;
                wmma::load_matrix_sync(ah[i], st + r * LDT + kk, LDT);
                wmma::load_matrix_sync(al[i], st + A_T + r * LDT + kk, LDT);
            }
#pragma unroll
            for (int j = 0; j < NJ; j++) {
                int c = wn * 16 * NJ + j * 16;
                wmma::load_matrix_sync(bh[j], st + 2 * A_T + c * LDT + kk, LDT);
                wmma::load_matrix_sync(bl[j], st + 2 * A_T + B_T + c * LDT + kk, LDT);
            }
#pragma unroll
            for (int i = 0; i < 4; i++)
#pragma unroll
                for (int j = 0; j < NJ; j++) {
                    wmma::mma_sync(acc[i][j], al[i], bh[j], acc[i][j]);
                    wmma::mma_sync(acc[i][j], ah[i], bl[j], acc[i][j]);
                    wmma::mma_sync(acc[i][j], ah[i], bh[j], acc[i][j]);
                }
        }
        s ^= 1;
    }

    // ---- epilogue ----
    if (OUTSPLIT) {
        __syncthreads();
#pragma unroll
        for (int i = 0; i < 4; i++)
#pragma unroll
            for (int j = 0; j < NJ; j++)
                wmma::store_matrix_sync(smf + (wm * 64 + i * 16) * LDCs + wn * 16 * NJ + j * 16,
                                        acc[i][j], LDCs, wmma::mem_row_major);
        __syncthreads();
        for (int e = t; e < 128 * BN; e += 256) {
            int r = e / BN, cn = e % BN;
            float v = smf[r * LDCs + cn];
            bf16 h = __float2bfloat16(v);
            long o = (m0 + r) * (long)N + n0 + cn;
            Chi[o] = h;
            Clo[o] = __float2bfloat16(v - __bfloat162float(h));
        }
    } else if (!GUARD) {
#pragma unroll
        for (int i = 0; i < 4; i++)
#pragma unroll
            for (int j = 0; j < NJ; j++)
                wmma::store_matrix_sync(
                    C + (m0 + wm * 64 + i * 16) * (long)N + n0 + wn * 16 * NJ + j * 16,
                    acc[i][j], N, wmma::mem_row_major);
    } else {
        __syncthreads();
        for (int half = 0; half < 2; half++) {
            if (wm == half) {
#pragma unroll
                for (int i = 0; i < 4; i++)
#pragma unroll
                    for (int j = 0; j < NJ; j++)
                        wmma::store_matrix_sync(smf + (i * 16) * LDCs + wn * 16 * NJ + j * 16,
                                                acc[i][j], LDCs, wmma::mem_row_major);
            }
            __syncthreads();
            for (int e = t; e < 64 * BN; e += 256) {
                int r = e / BN, cn = e % BN;
                int n = n0 + cn;
                if (n < N)
                    C[(m0 + half * 64 + r) * (long)N + n] = smf[r * LDCs + cn];
            }
            __syncthreads();
        }
    }
}

// ------- depthwise causal conv (dir-aware) + silu -> u hi/lo, 8 l's/thread -----
__global__ void conv_silu_kernel(const float* __restrict__ cw, const float* __restrict__ cb)
{
    const float L2E = 1.4426950408889634f;
    int t = blockIdx.x * blockDim.x + threadIdx.x;   // 2*B*(L/8)*DI = 2^20
    int d   = t & (DI - 1);
    int lq  = (t >> 9) & (L_ / 8 - 1);
    int b   = (t >> 17) & 3;
    int dir = (t >> 19) & 1;
    int l0  = lq * 8;
    const float* xi = g_xz + (size_t)dir * BL * 2 * DI;   // xi = first DI cols
    const float* w  = cw + (dir * DI + d) * 4;
    float w0 = w[0], w1 = w[1], w2 = w[2], w3 = w[3];
    float bv = cb[dir * DI + d];

    // load 11-value window of xi along l (coalesced across d)
    float v[11];
    if (dir == 0) {
        // taps l0-3 .. l0+7
#pragma unroll
        for (int i = 0; i < 11; i++) {
            int ll = l0 - 3 + i;
            v[i] = (ll >= 0) ? xi[((size_t)b * L_ + ll) * (2 * DI) + d] : 0.f;
        }
    } else {
        // taps l0 .. l0+10
#pragma unroll
        for (int i = 0; i < 11; i++) {
            int ll = l0 + i;
            v[i] = (ll < L_) ? xi[((size_t)b * L_ + ll) * (2 * DI) + d] : 0.f;
        }
    }

#pragma unroll
    for (int j = 0; j < 8; j++) {
        float acc = bv;
        if (dir == 0) {
            acc = fmaf(w0, v[j + 0], acc);
            acc = fmaf(w1, v[j + 1], acc);
            acc = fmaf(w2, v[j + 2], acc);
            acc = fmaf(w3, v[j + 3], acc);
        } else {
            acc = fmaf(w0, v[j + 3], acc);
            acc = fmaf(w1, v[j + 2], acc);
            acc = fmaf(w2, v[j + 1], acc);
            acc = fmaf(w3, v[j + 0], acc);
        }
        float uvv = acc * rcpf(1.f + ex2f(-acc * L2E));   // silu via rcp.approx
        size_t o = (size_t)dir * BL * DI + ((size_t)b * L_ + l0 + j) * DI + d;
        bf16 h = __float2bfloat16(uvv);
        g_uh[o] = h;
        g_ul[o] = __float2bfloat16(uvv - __bfloat162float(h));
    }
}

// ---------------- chunked selective scan, pass 1 ------------------------------
// dt fused; f32x2-packed recurrences; dbc K-slabs summed into smem per chunk.
__global__ void __launch_bounds__(128)
scan1_kernel(const float* __restrict__ A_log, const float* __restrict__ Dp,
             const float* __restrict__ dt_w, const float* __restrict__ dt_b)
{
    __shared__ float srow[LC * 48];       // 32 rows x 48 floats = 6 KB

    int bid = blockIdx.x;                 // 2048 = 2*4*64*4
    int dq  = bid & 3;
    int c   = (bid >> 2) & (NCH - 1);
    int b   = (bid >> 8) & 3;
    int dir = bid >> 10;
    int d   = dq * 128 + threadIdx.x;

    const bf16*  uhp = g_uh  + (size_t)dir * BL * DI;
    const bf16*  ulp = g_ul  + (size_t)dir * BL * DI;
    const float* zp  = g_xz  + (size_t)dir * BL * 2 * DI + DI;   // z half
    const float* dbp = g_dbc + (size_t)dir * BL * 48;            // K-slab 0

    // cooperative load of this chunk's 32 dbc rows, summing the two K-slabs
    {
        int l_lo = dir ? (L_ - LC - c * LC) : c * LC;
        const float4* g0 = (const float4*)(dbp + ((size_t)b * L_ + l_lo) * 48);
        const float4* g1 = (const float4*)((const float*)g0 + (size_t)2 * BL * 48);
        float4* s4 = (float4*)srow;
#pragma unroll
        for (int i = 0; i < 3; i++) {
            float4 a = g0[threadIdx.x + i * 128];
            float4 bq = g1[threadIdx.x + i * 128];
            s4[threadIdx.x + i * 128] =
                make_float4(a.x + bq.x, a.y + bq.y, a.z + bq.z, a.w + bq.w);
        }
    }
    __syncthreads();

    const float L2E = 1.4426950408889634f;
    const float LN2 = 0.6931471805599453f;
    float2 a2[NS / 2];
#pragma unroll
    for (int i = 0; i < NS / 2; i++) {
        const float* ap = A_log + (size_t)(dir * DI + d) * NS + 2 * i;
        a2[i] = make_float2(-__expf(ap[0]) * L2E, -__expf(ap[1]) * L2E);
    }
    const float Dv = Dp[dir * DI + d];

    float2 w2[RK / 2];
    {
        const float* wr = dt_w + (size_t)(dir * DI + d) * RK;
#pragma unroll
        for (int i = 0; i < RK / 2; i++) w2[i] = make_float2(wr[2 * i], wr[2 * i + 1]);
    }
    const float bb = dt_b[dir * DI + d];

    float2 h2[NS / 2], pp2[NS / 2], Kk2[NS / 2];
#pragma unroll
    for (int i = 0; i < NS / 2; i++) {
        h2[i] = make_float2(0.f, 0.f);
        pp2[i] = make_float2(1.f, 1.f);
        Kk2[i] = make_float2(0.f, 0.f);
    }
    float accl = 0.f;

    for (int j = 0; j < LC; j++) {
        int ss = c * LC + j;
        int l = dir ? (L_ - 1 - ss) : ss;
        size_t base = (size_t)b * L_ + l;
        float uv = __bfloat162float(uhp[base * DI + d]) + __bfloat162float(ulp[base * DI + d]);
        float zv = zp[base * 2 * DI + d];
        float gate = zv * rcpf(1.f + ex2f(-zv * L2E));

        int jr = dir ? (LC - 1 - j) : j;
        const float4* rr = (const float4*)(srow + jr * 48);
        float4 p0 = rr[0], p1 = rr[1], p2 = rr[2], p3 = rr[3];   // dt_lr
        float2 s2 = make_float2(bb, 0.f);
        s2 = fma2(make_float2(p0.x, p0.y), w2[0], s2);
        s2 = fma2(make_float2(p0.z, p0.w), w2[1], s2);
        s2 = fma2(make_float2(p1.x, p1.y), w2[2], s2);
        s2 = fma2(make_float2(p1.z, p1.w), w2[3], s2);
        s2 = fma2(make_float2(p2.x, p2.y), w2[4], s2);
        s2 = fma2(make_float2(p2.z, p2.w), w2[5], s2);
        s2 = fma2(make_float2(p3.x, p3.y), w2[6], s2);
        s2 = fma2(make_float2(p3.z, p3.w), w2[7], s2);
        float sdt = s2.x + s2.y;
        float dtv = (sdt > 15.f) ? sdt : LN2 * lg2f(1.f + ex2f(sdt * L2E));
        float x = dtv * uv;

        float4 q0 = rr[4], q1 = rr[5], q2 = rr[6], q3 = rr[7];   // B
        float4 q4 = rr[8], q5 = rr[9], q6 = rr[10], q7 = rr[11]; // C
        float2 Bv[8] = {{q0.x, q0.y}, {q0.z, q0.w}, {q1.x, q1.y}, {q1.z, q1.w},
                        {q2.x, q2.y}, {q2.z, q2.w}, {q3.x, q3.y}, {q3.z, q3.w}};
        float2 Cv[8] = {{q4.x, q4.y}, {q4.z, q4.w}, {q5.x, q5.y}, {q5.z, q5.w},
                        {q6.x, q6.y}, {q6.z, q6.w}, {q7.x, q7.y}, {q7.z, q7.w}};

        float2 dt2 = make_float2(dtv, dtv);
        float2 x2  = make_float2(x, x);
        float2 g2  = make_float2(gate, gate);
        float2 y2  = make_float2(0.f, 0.f);
#pragma unroll
        for (int i = 0; i < NS / 2; i++) {
            float2 m = mul2(dt2, a2[i]);
            float2 dA = make_float2(ex2f(m.x), ex2f(m.y));
            h2[i]  = fma2(dA, h2[i], mul2(x2, Bv[i]));
            pp2[i] = mul2(pp2[i], dA);
            y2     = fma2(h2[i], Cv[i], y2);
            Kk2[i] = fma2(mul2(g2, Cv[i]), pp2[i], Kk2[i]);
        }
        accl = fmaf(gate, fmaf(uv, Dv, y2.x + y2.y), accl);
    }

    size_t r = (((size_t)dir * NCH + c) * B_ + b) * DI + d;
    g_al[r] = accl;
#pragma unroll
    for (int i = 0; i < NS / 2; i++) {
        *(float2*)&g_S [r * NS + 2 * i] = h2[i];
        *(float2*)&g_P [r * NS + 2 * i] = pp2[i];
        *(float2*)&g_Kc[r * NS + 2 * i] = Kk2[i];
    }
}

// ---------------- scan combine: 16 lanes per (dir,b,d), shuffle-reduce --------
__global__ void scan2_kernel()
{
    int t = blockIdx.x * blockDim.x + threadIdx.x;   // 65536
    int n   = t & 15;
    int idx = t >> 4;        // 0..4095 = dir*2048 + b*512 + d
    int dir = idx >> 11;
    int b   = (idx >> 9) & 3;
    int d   = idx & (DI - 1);
    float hin = 0.f, acc = 0.f;
    for (int c = 0; c < NCH; c++) {
        size_t r = (((size_t)dir * NCH + c) * B_ + b) * DI + d;
        if (n == 0) acc += g_al[r];
        acc = fmaf(hin, g_Kc[r * NS + n], acc);
        hin = fmaf(g_P[r * NS + n], hin, g_S[r * NS + n]);
    }
#pragma unroll
    for (int o = 8; o; o >>= 1) acc += __shfl_down_sync(0xffffffffu, acc, o, 16);
    if (n == 0) g_pool[idx] = acc;
}

// ---------------- head: pooled @ out_w^T (per dir) -> embd --------------------
__global__ void head1_kernel(const float* __restrict__ out_w)
{
    int idx = blockIdx.x * blockDim.x + threadIdx.x;   // B * 512 = 2048
    if (idx >= B_ * 2 * HID) return;
    int b = idx >> 9;
    int cf = idx & 511;
    int dir = cf >> 8;
    int cc = cf & (HID - 1);
    const float* pr = g_pool + dir * B_ * DI + b * DI;
    const float* wr = out_w + ((size_t)dir * HID + cc) * DI;
    float s = 0.f;
#pragma unroll 8
    for (int k = 0; k < DI; k++) s = fmaf(pr[k], wr[k], s);
    g_embd[b * 512 + cf] = s * (1.f / (float)L_);
}

// ---------------- head: embd @ op_w^T + op_b ----------------------------------
__global__ void head2_kernel(const float* __restrict__ op_w, const float* __restrict__ op_b,
                             float* __restrict__ out)
{
    int idx = blockIdx.x * blockDim.x + threadIdx.x;   // B * 256 = 1024
    if (idx >= B_ * HID) return;
    int b = idx >> 8;
    int m = idx & (HID - 1);
    const float* e = g_embd + b * 512;
    const float* w = op_w + (size_t)m * 512;
    float s = op_b[m];
#pragma unroll 8
    for (int c = 0; c < 512; c++) s = fmaf(e[c], w[c], s);
    out[b * HID + m] = s;
}

// ------------------------------------------------------------------------------
extern "C" void kernel_launch(void* const* d_in, const int* in_sizes, int n_in,
                              void* d_out, int out_size)
{
    const float* x      = (const float*)d_in[0];
    const float* ip_w   = (const float*)d_in[1];
    const float* ip_b   = (const float*)d_in[2];
    const float* in_w   = (const float*)d_in[3];
    const float* conv_w = (const float*)d_in[4];
    const float* conv_b = (const float*)d_in[5];
    const float* xproj_w= (const float*)d_in[6];
    const float* dt_w   = (const float*)d_in[7];
    const float* dt_b   = (const float*)d_in[8];
    const float* A_log  = (const float*)d_in[9];
    const float* Dp     = (const float*)d_in[10];
    const float* out_w  = (const float*)d_in[11];
    const float* op_w   = (const float*)d_in[12];
    const float* op_b   = (const float*)d_in[13];
    float* out = (float*)d_out;

    float *pxz, *pdbc;
    bf16 *pxh, *pxl, *phh, *phl, *puh, *pul, *pipwh, *pipwl, *pinwh, *pinwl, *pxpwh, *pxpwl;
    cudaGetSymbolAddress((void**)&pxz,   g_xz);
    cudaGetSymbolAddress((void**)&pdbc,  g_dbc);
    cudaGetSymbolAddress((void**)&pxh,   g_xh);
    cudaGetSymbolAddress((void**)&pxl,   g_xl);
    cudaGetSymbolAddress((void**)&phh,   g_hh);
    cudaGetSymbolAddress((void**)&phl,   g_hl);
    cudaGetSymbolAddress((void**)&puh,   g_uh);
    cudaGetSymbolAddress((void**)&pul,   g_ul);
    cudaGetSymbolAddress((void**)&pipwh, g_ipwh);
    cudaGetSymbolAddress((void**)&pipwl, g_ipwl);
    cudaGetSymbolAddress((void**)&pinwh, g_inwh);
    cudaGetSymbolAddress((void**)&pinwl, g_inwl);
    cudaGetSymbolAddress((void**)&pxpwh, g_xpwh);
    cudaGetSymbolAddress((void**)&pxpwl, g_xpwl);

    const int smem1 = NSTG * (2 * 128 * LDT + 2 * 64 * LDT) * (int)sizeof(bf16);   // 61440
    const int smem2 = NSTG * (2 * 128 * LDT + 2 * 128 * LDT) * (int)sizeof(bf16);  // 81920
    cudaFuncSetAttribute(gemm_bf<2, false, true>,  cudaFuncAttributeMaxDynamicSharedMemorySize, smem2);
    cudaFuncSetAttribute(gemm_bf<2, false, false>, cudaFuncAttributeMaxDynamicSharedMemorySize, smem2);
    cudaFuncSetAttribute(gemm_bf<1, true, false>,  cudaFuncAttributeMaxDynamicSharedMemorySize, smem1);

    dim3 blk(256);
    const int n0 = BL * 512, n1 = HID * 512, n2 = 2 * 1024 * HID, n3 = 2 * 48 * 512;

    // 1) split x + all weights -> bf16 hi/lo (ONE launch, packed stores)
    split_all<<<((n0 + n1 + n2 + n3) / 8 + 255) / 256, 256>>>(
        x, pxh, pxl, n0,
        ip_w, pipwh, pipwl, n1,
        in_w, pinwh, pinwl, n2,
        xproj_w, pxpwh, pxpwl, n3);
    // 2) h = x @ ip_w^T + ip_b -> bf16 hi/lo directly   [8192,512]x[256,512], BN=128
    gemm_bf<2, false, true><<<dim3(HID / 128, BL / 128, 1), blk, smem2>>>(
        pxh, pxl, 0, pipwh, pipwl, 0, nullptr, phh, phl, 0, ip_b, BL, HID, 512, 0);
    // 3) xz_dir = h @ in_w[dir]^T   [8192,256]x[1024,256] -> [8192,1024] x2
    gemm_bf<2, false, false><<<dim3(1024 / 128, BL / 128, 2), blk, smem2>>>(
        phh, phl, 0, pinwh, pinwl, (long)1024 * HID, pxz, nullptr, nullptr, (long)BL * 1024,
        nullptr, BL, 1024, HID, 0);
    // 4) u = silu(depthwise causal conv(xi) + cb), 8 l's/thread (R15 version, PROFILED)
    conv_silu_kernel<<<(2 * BL * DI / 8) / 256, 256>>>(conv_w, conv_b);
    // 5) dbc_partial[ks] = u @ xproj_w[dir][:, ks*256:(ks+1)*256]^T  (K-split x2)
    gemm_bf<1, true, false><<<dim3(2, BL / 128, 2), blk, smem1>>>(
        puh, pul, (long)BL * DI, pxpwh, pxpwl, (long)48 * 512, pdbc, nullptr, nullptr,
        (long)BL * 48, nullptr, BL, 48, 256, (long)2 * BL * 48);
    // 6) chunked scan pass 1 (dt fused; K-slabs summed in smem; f32x2 recurrences)
    scan1_kernel<<<2048, 128>>>(A_log, Dp, dt_w, dt_b);
    // 7) chunk combine -> pooled sums
    scan2_kernel<<<256, 256>>>();
    // 8) pooled @ out_w^T (mean folded), concat dirs -> embd
    head1_kernel<<<8, 256>>>(out_w);
    // 9) embd @ op_w^T + op_b -> out
    head2_kernel<<<4, 256>>>(op_w, op_b, out);
}